// round 14
// baseline (speedup 1.0000x reference)
#include <cuda_runtime.h>
#include <cuda_fp16.h>

#define BATCH 4096
#define LSQ   64
#define HID   64
#define NFLD  11
#define LN    32
#define SROWS 32   // rows per CTA in k_seq (two 16-row MMA tiles)

// ---------------- scratch (no allocations allowed) ----------------
__device__ float g_m[2 * BATCH * HID];      // [from rows 0..4095 | to rows 4096..8191] x 64
__device__ float g_nwf[NFLD * BATCH * 8];   // [11][4096][8]

__constant__ int c_fm[11] = {0, 0, 1, 1, 2, 2, 3, 3, 4, 5, 5};

__device__ __forceinline__ float tanh_hw(float x) {
    float y; asm("tanh.approx.f32 %0, %1;" : "=f"(y) : "f"(x)); return y;
}
__device__ __forceinline__ float sig_hw(float x) {
    return fmaf(tanh_hw(0.5f * x), 0.5f, 0.5f);
}
__device__ __forceinline__ __half2 tanh_h2(__half2 x) {
    unsigned xi = *reinterpret_cast<unsigned*>(&x), yi;
    asm("tanh.approx.f16x2 %0, %1;" : "=r"(yi) : "r"(xi));
    return *reinterpret_cast<__half2*>(&yi);
}

// LSTM activation for a PAIR of cells using f16x2 MUFU (5 MUFU per 2 cells).
// Gates pass through fp16; c stays fp32. Returns h pair as half2 (store-ready).
__device__ __forceinline__ __half2 lstm_pair(float di0, float di1, float df0, float df1,
                                             float dg0, float dg1, float do0, float do1,
                                             float& c0, float& c1) {
    const __half2 h05 = __floats2half2_rn(0.5f, 0.5f);
    __half2 si = __hfma2(tanh_h2(__hmul2(__floats2half2_rn(di0, di1), h05)), h05, h05);
    __half2 sf = __hfma2(tanh_h2(__hmul2(__floats2half2_rn(df0, df1), h05)), h05, h05);
    __half2 tg = tanh_h2(__floats2half2_rn(dg0, dg1));
    __half2 so = __hfma2(tanh_h2(__hmul2(__floats2half2_rn(do0, do1), h05)), h05, h05);
    float2 fi = __half22float2(si);
    float2 ff = __half22float2(sf);
    float2 fg = __half22float2(tg);
    c0 = fmaf(ff.x, c0, fi.x * fg.x);
    c1 = fmaf(ff.y, c1, fi.y * fg.y);
    __half2 tc = tanh_h2(__floats2half2_rn(c0, c1));
    return __hmul2(so, tc);
}

// ---------------- kernel 1: tensor-core sequence LSTM ----------------
// Tile-sequential structure (tile0 MMA->act->store, then tile1) to cap live
// accumulators at 16, making room for f16x2 activation packing under the
// occ-2 128-reg budget. MUFU per warp-step: 40 -> 20.
__global__ void __launch_bounds__(256, 2) k_seq(const int* __restrict__ from_seq,
                                                const int* __restrict__ to_seq,
                                                const float* __restrict__ Wh,
                                                const float* __restrict__ Wx,
                                                const float* __restrict__ bias,
                                                const float* __restrict__ base_emb) {
    const int tid  = threadIdx.x;
    const int lane = tid & 31;
    const int w    = tid >> 5;
    const int gid  = lane >> 2;
    const int tig  = lane & 3;
    const int row0 = blockIdx.x * SROWS;

    __shared__ __half  hbuf[2][SROWS][88];
    __shared__ int     tok[SROWS][LSQ];
    __shared__ __half2 ebase[85][3];

    const int* seq = (row0 < BATCH) ? (from_seq + row0 * LSQ)
                                    : (to_seq + (row0 - BATCH) * LSQ);
    for (int i = tid; i < SROWS * LSQ; i += 256) tok[i >> 6][i & 63] = seq[i];
    for (int i = tid; i < 2 * SROWS * 88; i += 256)
        (&hbuf[0][0][0])[i] = __float2half(0.0f);
    for (int i = tid; i < 85 * 3; i += 256) {
        int v = i / 3, p = i % 3;
        ebase[v][p] = __floats2half2_rn(base_emb[v * 6 + 2 * p], base_emb[v * 6 + 2 * p + 1]);
    }
    __syncthreads();
    if (tid < 64) hbuf[tid >> 5][tid & 31][70] = __float2half(1.0f);
    if (tid < 96) {
        int r = tid / 3, p = tid % 3;
        *reinterpret_cast<__half2*>(&hbuf[0][r][64 + 2 * p]) = ebase[tok[r][0]][p];
    }

    unsigned bfr[4][5][2];
#pragma unroll
    for (int g = 0; g < 4; g++) {
        const int col = 64 * g + 8 * w + gid;
#pragma unroll
        for (int kt = 0; kt < 4; kt++) {
            int k0 = 16 * kt + 2 * tig;
            __half2 b0 = __floats2half2_rn(Wh[k0 * 256 + col], Wh[(k0 + 1) * 256 + col]);
            __half2 b1 = __floats2half2_rn(Wh[(k0 + 8) * 256 + col], Wh[(k0 + 9) * 256 + col]);
            bfr[g][kt][0] = *reinterpret_cast<unsigned*>(&b0);
            bfr[g][kt][1] = *reinterpret_cast<unsigned*>(&b1);
        }
        {
            int r0 = 64 + 2 * tig;
            float v0 = (r0 < 70) ? Wx[(r0 - 64) * 256 + col] : ((r0 == 70) ? bias[col] : 0.0f);
            float v1 = (r0 + 1 < 70) ? Wx[(r0 - 63) * 256 + col] : ((r0 + 1 == 70) ? bias[col] : 0.0f);
            __half2 b0 = __floats2half2_rn(v0, v1);
            bfr[g][4][0] = *reinterpret_cast<unsigned*>(&b0);
            bfr[g][4][1] = 0u;
        }
    }

    const int hc0 = 8 * w + 2 * tig;
    const int arow = (lane < 16) ? lane : (lane - 16);
    const int acol = (lane < 16) ? 0 : 8;
    const unsigned a00 = (unsigned)__cvta_generic_to_shared(&hbuf[0][arow][acol]);
    const unsigned a01 = (unsigned)__cvta_generic_to_shared(&hbuf[0][16 + arow][acol]);
    const unsigned a10 = (unsigned)__cvta_generic_to_shared(&hbuf[1][arow][acol]);
    const unsigned a11 = (unsigned)__cvta_generic_to_shared(&hbuf[1][16 + arow][acol]);

    float cst[8] = {0.0f, 0.0f, 0.0f, 0.0f, 0.0f, 0.0f, 0.0f, 0.0f};

    __syncthreads();

    for (int t = 0; t < LSQ; t++) {
        const unsigned wb = (t & 1) ^ 1;

#pragma unroll
        for (int tile = 0; tile < 2; tile++) {
            const unsigned ra = (t & 1) ? ((tile == 0) ? a10 : a11)
                                        : ((tile == 0) ? a00 : a01);

            float d[4][4];
#pragma unroll
            for (int g = 0; g < 4; g++)
#pragma unroll
                for (int q = 0; q < 4; q++) d[g][q] = 0.0f;

#pragma unroll
            for (int kt = 0; kt < 5; kt++) {
                unsigned ah[4];
                asm volatile("ldmatrix.sync.aligned.m8n8.x4.shared.b16 {%0,%1,%2,%3}, [%4];\n"
                             : "=r"(ah[0]), "=r"(ah[1]), "=r"(ah[2]), "=r"(ah[3])
                             : "r"(ra + kt * 32));
#pragma unroll
                for (int g = 0; g < 4; g++) {
                    asm("mma.sync.aligned.m16n8k16.row.col.f32.f16.f16.f32 "
                        "{%0,%1,%2,%3},{%4,%5,%6,%7},{%8,%9},{%0,%1,%2,%3};\n"
                        : "+f"(d[g][0]), "+f"(d[g][1]), "+f"(d[g][2]), "+f"(d[g][3])
                        : "r"(ah[0]), "r"(ah[1]), "r"(ah[2]), "r"(ah[3]),
                          "r"(bfr[g][kt][0]), "r"(bfr[g][kt][1]));
                }
            }

            // f16x2 activations: 5 MUFU per 2 cells
            const int cb = tile * 4;
            __half2 hA = lstm_pair(d[0][0], d[0][1], d[1][0], d[1][1],
                                   d[2][0], d[2][1], d[3][0], d[3][1],
                                   cst[cb + 0], cst[cb + 1]);
            __half2 hB = lstm_pair(d[0][2], d[0][3], d[1][2], d[1][3],
                                   d[2][2], d[2][3], d[3][2], d[3][3],
                                   cst[cb + 2], cst[cb + 3]);

            const int rA = gid + tile * 16;
            const int rB = gid + 8 + tile * 16;
            *reinterpret_cast<__half2*>(&hbuf[wb][rA][hc0]) = hA;
            *reinterpret_cast<__half2*>(&hbuf[wb][rB][hc0]) = hB;

            if (t == LSQ - 1) {
                *reinterpret_cast<float2*>(&g_m[(row0 + rA) * 64 + hc0]) = __half22float2(hA);
                *reinterpret_cast<float2*>(&g_m[(row0 + rB) * 64 + hc0]) = __half22float2(hB);
            }
        }

        if (t < LSQ - 1 && tid < 96) {
            int r = tid / 3, p = tid % 3;
            *reinterpret_cast<__half2*>(&hbuf[wb][r][64 + 2 * p]) = ebase[tok[r][t + 1]][p];
        }
        __syncthreads();
    }
}

// ---------------- kernel 2: tensor-core NWF LSTMs (unchanged) ----------------
__global__ void __launch_bounds__(256, 2) k_nwf(const int* __restrict__ nums_g,
                                                const int* __restrict__ frs_g,
                                                const float* __restrict__ ne_g,
                                                const float* __restrict__ fe_g,
                                                const float* __restrict__ Wx_g,
                                                const float* __restrict__ Wh_g,
                                                const float* __restrict__ b_g) {
    const int tid  = threadIdx.x;
    const int lane = tid & 31;
    const int w    = tid >> 5;
    const int gid  = lane >> 2;
    const int tig  = lane & 3;
    const int field = blockIdx.y;
    const int m = c_fm[field];
    const int row0 = blockIdx.x * 128;

    __shared__ int    ns[LN][132];
    __shared__ int    fs[LN][132];
    __shared__ __half At[8][16][24];

    const int base = (field * BATCH + row0) * LN;
    for (int i = tid; i < 128 * LN; i += 256) {
        int r = i >> 5, t = i & 31;
        ns[t][r] = nums_g[base + i];
        fs[t][r] = frs_g[base + i];
    }
    for (int i = tid; i < 8 * 16 * 24 / 2; i += 256)
        reinterpret_cast<__half2*>(&At[0][0][0])[i] = __floats2half2_rn(0.0f, 0.0f);
    __syncthreads();

    unsigned bf[4][2];
    float2 b2[4];
#pragma unroll
    for (int g = 0; g < 4; g++) {
        const int col = 8 * g + gid;
        __half2 x0 = __floats2half2_rn(Wx_g[m * 256 + (2 * tig) * 32 + col],
                                       Wx_g[m * 256 + (2 * tig + 1) * 32 + col]);
        __half2 h0 = __floats2half2_rn(Wh_g[m * 256 + (2 * tig) * 32 + col],
                                       Wh_g[m * 256 + (2 * tig + 1) * 32 + col]);
        bf[g][0] = *reinterpret_cast<unsigned*>(&x0);
        bf[g][1] = *reinterpret_cast<unsigned*>(&h0);
        b2[g] = make_float2(b_g[m * 32 + 8 * g + 2 * tig], b_g[m * 32 + 8 * g + 2 * tig + 1]);
    }

    const float4* neg = reinterpret_cast<const float4*>(ne_g) + m * 1000;
    const float4* feg = reinterpret_cast<const float4*>(fe_g) + m * 1000;

    const int lrow = lane & 15;
    const bool isNe = (lane < 16);
    const int myrow = w * 16 + lrow;
    const int xcol = isNe ? 0 : 4;
    const unsigned aaddr = (unsigned)__cvta_generic_to_shared(&At[w][lrow][isNe ? 0 : 8]);

    float cst[4] = {0.0f, 0.0f, 0.0f, 0.0f};
    float hv[4] = {0.0f, 0.0f, 0.0f, 0.0f};

    for (int t = 0; t < LN; t++) {
        int idx = isNe ? ns[t][myrow] : fs[t][myrow];
        float4 v = __ldg(isNe ? &neg[idx] : &feg[idx]);
        *reinterpret_cast<__half2*>(&At[w][lrow][xcol])     = __floats2half2_rn(v.x, v.y);
        *reinterpret_cast<__half2*>(&At[w][lrow][xcol + 2]) = __floats2half2_rn(v.z, v.w);
        __syncwarp();

        unsigned a[4];
        asm volatile("ldmatrix.sync.aligned.m8n8.x4.shared.b16 {%0,%1,%2,%3}, [%4];\n"
                     : "=r"(a[0]), "=r"(a[1]), "=r"(a[2]), "=r"(a[3]) : "r"(aaddr));

        float d[4][4];
#pragma unroll
        for (int g = 0; g < 4; g++) {
            d[g][0] = 0.0f; d[g][1] = 0.0f; d[g][2] = 0.0f; d[g][3] = 0.0f;
            asm("mma.sync.aligned.m16n8k16.row.col.f32.f16.f16.f32 "
                "{%0,%1,%2,%3},{%4,%5,%6,%7},{%8,%9},{%0,%1,%2,%3};\n"
                : "+f"(d[g][0]), "+f"(d[g][1]), "+f"(d[g][2]), "+f"(d[g][3])
                : "r"(a[0]), "r"(a[1]), "r"(a[2]), "r"(a[3]),
                  "r"(bf[g][0]), "r"(bf[g][1]));
        }

#pragma unroll
        for (int q = 0; q < 4; q++) {
            float bi = (q & 1) ? b2[0].y : b2[0].x;
            float bff = (q & 1) ? b2[1].y : b2[1].x;
            float bgg = (q & 1) ? b2[2].y : b2[2].x;
            float bo = (q & 1) ? b2[3].y : b2[3].x;
            float gi = d[0][q] + bi, gf = d[1][q] + bff, gg = d[2][q] + bgg, go = d[3][q] + bo;
            cst[q] = sig_hw(gf) * cst[q] + sig_hw(gi) * tanh_hw(gg);
            hv[q]  = sig_hw(go) * tanh_hw(cst[q]);
        }

        *reinterpret_cast<__half2*>(&At[w][gid][8 + 2 * tig])     = __floats2half2_rn(hv[0], hv[1]);
        *reinterpret_cast<__half2*>(&At[w][gid + 8][8 + 2 * tig]) = __floats2half2_rn(hv[2], hv[3]);
    }

    float* o = &g_nwf[(field * BATCH + row0 + w * 16) * 8];
    *reinterpret_cast<float2*>(&o[gid * 8 + 2 * tig])       = make_float2(hv[0], hv[1]);
    *reinterpret_cast<float2*>(&o[(gid + 8) * 8 + 2 * tig]) = make_float2(hv[2], hv[3]);
}

// ---------------- kernel 3: feature concat + dense 234->64 + ReLU (unchanged R13) ----------------
__global__ void __launch_bounds__(512) k_final(const float* __restrict__ goby_emb,
                                               const float* __restrict__ bool_emb,
                                               const float* __restrict__ count_emb,
                                               const float* __restrict__ W,
                                               const float* __restrict__ bias,
                                               const int* __restrict__ goby_idx,
                                               const int* __restrict__ is_indel,
                                               const int* __restrict__ matches_ref,
                                               const int* __restrict__ count_fwd,
                                               const int* __restrict__ count_rev,
                                               float* __restrict__ out) {
    const int tid = threadIdx.x;
    const int row0 = blockIdx.x * 32;
    __shared__ float fsh[32][240];

    for (int i = tid; i < 32 * 234; i += 512) {
        int rr = i / 234, f = i % 234;
        int row = row0 + rr;
        float v;
        if (f < 4)        v = goby_emb[goby_idx[row] * 4 + f];
        else if (f < 6)   v = bool_emb[is_indel[row] * 2 + (f - 4)];
        else if (f < 8)   v = bool_emb[matches_ref[row] * 2 + (f - 6)];
        else if (f < 72)  v = g_m[row * 64 + (f - 8)];
        else if (f < 136) v = g_m[(BATCH + row) * 64 + (f - 72)];
        else if (f < 141) v = count_emb[count_fwd[row] * 5 + (f - 136)];
        else if (f < 146) v = count_emb[count_rev[row] * 5 + (f - 141)];
        else {
            int ff = f - 146;
            v = g_nwf[((ff >> 3) * BATCH + row) * 8 + (ff & 7)];
        }
        fsh[rr][f] = v;
    }
    __syncthreads();

    const int rr = tid >> 4;
    const int cq = tid & 15;
    const float4* W4 = reinterpret_cast<const float4*>(W);
    float4 acc = __ldg(reinterpret_cast<const float4*>(bias) + cq);
#pragma unroll 6
    for (int f = 0; f < 234; f++) {
        float v = fsh[rr][f];
        float4 wv = __ldg(&W4[f * 16 + cq]);
        acc.x = fmaf(v, wv.x, acc.x);
        acc.y = fmaf(v, wv.y, acc.y);
        acc.z = fmaf(v, wv.z, acc.z);
        acc.w = fmaf(v, wv.w, acc.w);
    }
    *reinterpret_cast<float4*>(&out[(row0 + rr) * 64 + 4 * cq]) =
        make_float4(fmaxf(acc.x, 0.0f), fmaxf(acc.y, 0.0f),
                    fmaxf(acc.z, 0.0f), fmaxf(acc.w, 0.0f));
}

// ---------------- launch (serial) ----------------
extern "C" void kernel_launch(void* const* d_in, const int* in_sizes, int n_in,
                              void* d_out, int out_size) {
    static const int dictmap[23]  = {0,1,2,3,4,5,6,7,8,9,10,11,12,13,14,15,16,17,18,19,20,21,22};
    static const int parammap[23] = {14,15,16,17,18,19,20,21,22,0,1,2,3,4,5,6,7,8,9,10,11,12,13};
    const int* mp = (in_sizes[0] == BATCH) ? dictmap : parammap;

    const int*   goby_idx     = (const int*)  d_in[mp[0]];
    const int*   is_indel     = (const int*)  d_in[mp[1]];
    const int*   matches_ref  = (const int*)  d_in[mp[2]];
    const int*   from_seq     = (const int*)  d_in[mp[3]];
    const int*   to_seq       = (const int*)  d_in[mp[4]];
    const int*   count_fwd    = (const int*)  d_in[mp[5]];
    const int*   count_rev    = (const int*)  d_in[mp[6]];
    const int*   nwf_numbers  = (const int*)  d_in[mp[7]];
    const int*   nwf_freqs    = (const int*)  d_in[mp[8]];
    const float* goby_emb     = (const float*)d_in[mp[9]];
    const float* bool_emb     = (const float*)d_in[mp[10]];
    const float* count_emb    = (const float*)d_in[mp[11]];
    const float* base_emb     = (const float*)d_in[mp[12]];
    const float* seq_Wx       = (const float*)d_in[mp[13]];
    const float* seq_Wh       = (const float*)d_in[mp[14]];
    const float* seq_b        = (const float*)d_in[mp[15]];
    const float* nwf_num_emb  = (const float*)d_in[mp[16]];
    const float* nwf_freq_emb = (const float*)d_in[mp[17]];
    const float* nwf_Wx       = (const float*)d_in[mp[18]];
    const float* nwf_Wh       = (const float*)d_in[mp[19]];
    const float* nwf_b        = (const float*)d_in[mp[20]];
    const float* reduce_W     = (const float*)d_in[mp[21]];
    const float* reduce_b     = (const float*)d_in[mp[22]];

    k_seq<<<(2 * BATCH) / SROWS, 256>>>(from_seq, to_seq, seq_Wh, seq_Wx, seq_b, base_emb);
    k_nwf<<<dim3(BATCH / 128, NFLD), 256>>>(nwf_numbers, nwf_freqs,
                                            nwf_num_emb, nwf_freq_emb,
                                            nwf_Wx, nwf_Wh, nwf_b);
    k_final<<<BATCH / 32, 512>>>(goby_emb, bool_emb, count_emb, reduce_W, reduce_b,
                                 goby_idx, is_indel, matches_ref, count_fwd, count_rev,
                                 (float*)d_out);
}

// round 15
// speedup vs baseline: 1.1902x; 1.1902x over previous
#include <cuda_runtime.h>
#include <cuda_fp16.h>

#define BATCH 4096
#define LSQ   64
#define HID   64
#define NFLD  11
#define LN    32
#define SROWS 32   // rows per CTA in k_seq (two 16-row MMA tiles)

// ---------------- scratch (no allocations allowed) ----------------
__device__ float g_m[2 * BATCH * HID];      // [from rows 0..4095 | to rows 4096..8191] x 64
__device__ float g_nwf[NFLD * BATCH * 8];   // [11][4096][8]

__constant__ int c_fm[11] = {0, 0, 1, 1, 2, 2, 3, 3, 4, 5, 5};

__device__ __forceinline__ float tanh_hw(float x) {
    float y; asm("tanh.approx.f32 %0, %1;" : "=f"(y) : "f"(x)); return y;
}
__device__ __forceinline__ float sig_hw(float x) {
    return fmaf(tanh_hw(0.5f * x), 0.5f, 0.5f);
}

// ---------------- kernel 1: tensor-core sequence LSTM (proven 82.8us config) ----------------
__global__ void __launch_bounds__(256, 2) k_seq(const int* __restrict__ from_seq,
                                                const int* __restrict__ to_seq,
                                                const float* __restrict__ Wh,
                                                const float* __restrict__ Wx,
                                                const float* __restrict__ bias,
                                                const float* __restrict__ base_emb) {
    const int tid  = threadIdx.x;
    const int lane = tid & 31;
    const int w    = tid >> 5;
    const int gid  = lane >> 2;
    const int tig  = lane & 3;
    const int row0 = blockIdx.x * SROWS;

    __shared__ __half  hbuf[2][SROWS][88];
    __shared__ int     tok[SROWS][LSQ];
    __shared__ __half2 ebase[85][3];

    const int* seq = (row0 < BATCH) ? (from_seq + row0 * LSQ)
                                    : (to_seq + (row0 - BATCH) * LSQ);
    for (int i = tid; i < SROWS * LSQ; i += 256) tok[i >> 6][i & 63] = seq[i];
    for (int i = tid; i < 2 * SROWS * 88; i += 256)
        (&hbuf[0][0][0])[i] = __float2half(0.0f);
    for (int i = tid; i < 85 * 3; i += 256) {
        int v = i / 3, p = i % 3;
        ebase[v][p] = __floats2half2_rn(base_emb[v * 6 + 2 * p], base_emb[v * 6 + 2 * p + 1]);
    }
    __syncthreads();
    if (tid < 64) hbuf[tid >> 5][tid & 31][70] = __float2half(1.0f);
    if (tid < 96) {
        int r = tid / 3, p = tid % 3;
        *reinterpret_cast<__half2*>(&hbuf[0][r][64 + 2 * p]) = ebase[tok[r][0]][p];
    }

    unsigned bfr[4][5][2];
#pragma unroll
    for (int g = 0; g < 4; g++) {
        const int col = 64 * g + 8 * w + gid;
#pragma unroll
        for (int kt = 0; kt < 4; kt++) {
            int k0 = 16 * kt + 2 * tig;
            __half2 b0 = __floats2half2_rn(Wh[k0 * 256 + col], Wh[(k0 + 1) * 256 + col]);
            __half2 b1 = __floats2half2_rn(Wh[(k0 + 8) * 256 + col], Wh[(k0 + 9) * 256 + col]);
            bfr[g][kt][0] = *reinterpret_cast<unsigned*>(&b0);
            bfr[g][kt][1] = *reinterpret_cast<unsigned*>(&b1);
        }
        {
            int r0 = 64 + 2 * tig;
            float v0 = (r0 < 70) ? Wx[(r0 - 64) * 256 + col] : ((r0 == 70) ? bias[col] : 0.0f);
            float v1 = (r0 + 1 < 70) ? Wx[(r0 - 63) * 256 + col] : ((r0 + 1 == 70) ? bias[col] : 0.0f);
            __half2 b0 = __floats2half2_rn(v0, v1);
            bfr[g][4][0] = *reinterpret_cast<unsigned*>(&b0);
            bfr[g][4][1] = 0u;
        }
    }

    const int hc0 = 8 * w + 2 * tig;
    const int arow = (lane < 16) ? lane : (lane - 16);
    const int acol = (lane < 16) ? 0 : 8;
    const unsigned a00 = (unsigned)__cvta_generic_to_shared(&hbuf[0][arow][acol]);
    const unsigned a01 = (unsigned)__cvta_generic_to_shared(&hbuf[0][16 + arow][acol]);
    const unsigned a10 = (unsigned)__cvta_generic_to_shared(&hbuf[1][arow][acol]);
    const unsigned a11 = (unsigned)__cvta_generic_to_shared(&hbuf[1][16 + arow][acol]);

    float cst[8] = {0.0f, 0.0f, 0.0f, 0.0f, 0.0f, 0.0f, 0.0f, 0.0f};

    __syncthreads();

    for (int t = 0; t < LSQ; t++) {
        const unsigned r0a = (t & 1) ? a10 : a00;
        const unsigned r1a = (t & 1) ? a11 : a01;

        float d0[4][4], d1[4][4];
#pragma unroll
        for (int g = 0; g < 4; g++)
#pragma unroll
            for (int q = 0; q < 4; q++) { d0[g][q] = 0.0f; d1[g][q] = 0.0f; }

#pragma unroll
        for (int kt = 0; kt < 5; kt++) {
            unsigned ah0[4], ah1[4];
            asm volatile("ldmatrix.sync.aligned.m8n8.x4.shared.b16 {%0,%1,%2,%3}, [%4];\n"
                         : "=r"(ah0[0]), "=r"(ah0[1]), "=r"(ah0[2]), "=r"(ah0[3])
                         : "r"(r0a + kt * 32));
            asm volatile("ldmatrix.sync.aligned.m8n8.x4.shared.b16 {%0,%1,%2,%3}, [%4];\n"
                         : "=r"(ah1[0]), "=r"(ah1[1]), "=r"(ah1[2]), "=r"(ah1[3])
                         : "r"(r1a + kt * 32));
#pragma unroll
            for (int g = 0; g < 4; g++) {
                asm("mma.sync.aligned.m16n8k16.row.col.f32.f16.f16.f32 "
                    "{%0,%1,%2,%3},{%4,%5,%6,%7},{%8,%9},{%0,%1,%2,%3};\n"
                    : "+f"(d0[g][0]), "+f"(d0[g][1]), "+f"(d0[g][2]), "+f"(d0[g][3])
                    : "r"(ah0[0]), "r"(ah0[1]), "r"(ah0[2]), "r"(ah0[3]),
                      "r"(bfr[g][kt][0]), "r"(bfr[g][kt][1]));
                asm("mma.sync.aligned.m16n8k16.row.col.f32.f16.f16.f32 "
                    "{%0,%1,%2,%3},{%4,%5,%6,%7},{%8,%9},{%0,%1,%2,%3};\n"
                    : "+f"(d1[g][0]), "+f"(d1[g][1]), "+f"(d1[g][2]), "+f"(d1[g][3])
                    : "r"(ah1[0]), "r"(ah1[1]), "r"(ah1[2]), "r"(ah1[3]),
                      "r"(bfr[g][kt][0]), "r"(bfr[g][kt][1]));
            }
        }

        float hv[8];
#pragma unroll
        for (int q = 0; q < 4; q++) {
            cst[q] = sig_hw(d0[1][q]) * cst[q] + sig_hw(d0[0][q]) * tanh_hw(d0[2][q]);
            hv[q]  = sig_hw(d0[3][q]) * tanh_hw(cst[q]);
        }
#pragma unroll
        for (int q = 0; q < 4; q++) {
            cst[4 + q] = sig_hw(d1[1][q]) * cst[4 + q] + sig_hw(d1[0][q]) * tanh_hw(d1[2][q]);
            hv[4 + q]  = sig_hw(d1[3][q]) * tanh_hw(cst[4 + q]);
        }

        const int wb = (t & 1) ^ 1;
        *reinterpret_cast<__half2*>(&hbuf[wb][gid][hc0])      = __floats2half2_rn(hv[0], hv[1]);
        *reinterpret_cast<__half2*>(&hbuf[wb][gid + 8][hc0])  = __floats2half2_rn(hv[2], hv[3]);
        *reinterpret_cast<__half2*>(&hbuf[wb][gid + 16][hc0]) = __floats2half2_rn(hv[4], hv[5]);
        *reinterpret_cast<__half2*>(&hbuf[wb][gid + 24][hc0]) = __floats2half2_rn(hv[6], hv[7]);
        if (t < LSQ - 1 && tid < 96) {
            int r = tid / 3, p = tid % 3;
            *reinterpret_cast<__half2*>(&hbuf[wb][r][64 + 2 * p]) = ebase[tok[r][t + 1]][p];
        }

        if (t == LSQ - 1) {
            *reinterpret_cast<float2*>(&g_m[(row0 + gid) * 64 + hc0])      = make_float2(hv[0], hv[1]);
            *reinterpret_cast<float2*>(&g_m[(row0 + gid + 8) * 64 + hc0])  = make_float2(hv[2], hv[3]);
            *reinterpret_cast<float2*>(&g_m[(row0 + gid + 16) * 64 + hc0]) = make_float2(hv[4], hv[5]);
            *reinterpret_cast<float2*>(&g_m[(row0 + gid + 24) * 64 + hc0]) = make_float2(hv[6], hv[7]);
        }
        __syncthreads();
    }
}

// ---------------- kernel 2: tensor-core NWF LSTMs (proven config) ----------------
__global__ void __launch_bounds__(256, 2) k_nwf(const int* __restrict__ nums_g,
                                                const int* __restrict__ frs_g,
                                                const float* __restrict__ ne_g,
                                                const float* __restrict__ fe_g,
                                                const float* __restrict__ Wx_g,
                                                const float* __restrict__ Wh_g,
                                                const float* __restrict__ b_g) {
    const int tid  = threadIdx.x;
    const int lane = tid & 31;
    const int w    = tid >> 5;
    const int gid  = lane >> 2;
    const int tig  = lane & 3;
    const int field = blockIdx.y;
    const int m = c_fm[field];
    const int row0 = blockIdx.x * 128;

    __shared__ int    ns[LN][132];
    __shared__ int    fs[LN][132];
    __shared__ __half At[8][16][24];

    const int base = (field * BATCH + row0) * LN;
    for (int i = tid; i < 128 * LN; i += 256) {
        int r = i >> 5, t = i & 31;
        ns[t][r] = nums_g[base + i];
        fs[t][r] = frs_g[base + i];
    }
    for (int i = tid; i < 8 * 16 * 24 / 2; i += 256)
        reinterpret_cast<__half2*>(&At[0][0][0])[i] = __floats2half2_rn(0.0f, 0.0f);
    __syncthreads();

    unsigned bf[4][2];
    float2 b2[4];
#pragma unroll
    for (int g = 0; g < 4; g++) {
        const int col = 8 * g + gid;
        __half2 x0 = __floats2half2_rn(Wx_g[m * 256 + (2 * tig) * 32 + col],
                                       Wx_g[m * 256 + (2 * tig + 1) * 32 + col]);
        __half2 h0 = __floats2half2_rn(Wh_g[m * 256 + (2 * tig) * 32 + col],
                                       Wh_g[m * 256 + (2 * tig + 1) * 32 + col]);
        bf[g][0] = *reinterpret_cast<unsigned*>(&x0);
        bf[g][1] = *reinterpret_cast<unsigned*>(&h0);
        b2[g] = make_float2(b_g[m * 32 + 8 * g + 2 * tig], b_g[m * 32 + 8 * g + 2 * tig + 1]);
    }

    const float4* neg = reinterpret_cast<const float4*>(ne_g) + m * 1000;
    const float4* feg = reinterpret_cast<const float4*>(fe_g) + m * 1000;

    const int lrow = lane & 15;
    const bool isNe = (lane < 16);
    const int myrow = w * 16 + lrow;
    const int xcol = isNe ? 0 : 4;
    const unsigned aaddr = (unsigned)__cvta_generic_to_shared(&At[w][lrow][isNe ? 0 : 8]);

    float cst[4] = {0.0f, 0.0f, 0.0f, 0.0f};
    float hv[4] = {0.0f, 0.0f, 0.0f, 0.0f};

    for (int t = 0; t < LN; t++) {
        int idx = isNe ? ns[t][myrow] : fs[t][myrow];
        float4 v = __ldg(isNe ? &neg[idx] : &feg[idx]);
        *reinterpret_cast<__half2*>(&At[w][lrow][xcol])     = __floats2half2_rn(v.x, v.y);
        *reinterpret_cast<__half2*>(&At[w][lrow][xcol + 2]) = __floats2half2_rn(v.z, v.w);
        __syncwarp();

        unsigned a[4];
        asm volatile("ldmatrix.sync.aligned.m8n8.x4.shared.b16 {%0,%1,%2,%3}, [%4];\n"
                     : "=r"(a[0]), "=r"(a[1]), "=r"(a[2]), "=r"(a[3]) : "r"(aaddr));

        float d[4][4];
#pragma unroll
        for (int g = 0; g < 4; g++) {
            d[g][0] = 0.0f; d[g][1] = 0.0f; d[g][2] = 0.0f; d[g][3] = 0.0f;
            asm("mma.sync.aligned.m16n8k16.row.col.f32.f16.f16.f32 "
                "{%0,%1,%2,%3},{%4,%5,%6,%7},{%8,%9},{%0,%1,%2,%3};\n"
                : "+f"(d[g][0]), "+f"(d[g][1]), "+f"(d[g][2]), "+f"(d[g][3])
                : "r"(a[0]), "r"(a[1]), "r"(a[2]), "r"(a[3]),
                  "r"(bf[g][0]), "r"(bf[g][1]));
        }

#pragma unroll
        for (int q = 0; q < 4; q++) {
            float bi = (q & 1) ? b2[0].y : b2[0].x;
            float bff = (q & 1) ? b2[1].y : b2[1].x;
            float bgg = (q & 1) ? b2[2].y : b2[2].x;
            float bo = (q & 1) ? b2[3].y : b2[3].x;
            float gi = d[0][q] + bi, gf = d[1][q] + bff, gg = d[2][q] + bgg, go = d[3][q] + bo;
            cst[q] = sig_hw(gf) * cst[q] + sig_hw(gi) * tanh_hw(gg);
            hv[q]  = sig_hw(go) * tanh_hw(cst[q]);
        }

        *reinterpret_cast<__half2*>(&At[w][gid][8 + 2 * tig])     = __floats2half2_rn(hv[0], hv[1]);
        *reinterpret_cast<__half2*>(&At[w][gid + 8][8 + 2 * tig]) = __floats2half2_rn(hv[2], hv[3]);
    }

    float* o = &g_nwf[(field * BATCH + row0 + w * 16) * 8];
    *reinterpret_cast<float2*>(&o[gid * 8 + 2 * tig])       = make_float2(hv[0], hv[1]);
    *reinterpret_cast<float2*>(&o[(gid + 8) * 8 + 2 * tig]) = make_float2(hv[2], hv[3]);
}

// ---------------- kernel 3: slot-staged concat + dense 234->64 + ReLU ----------------
// 16 rows/CTA, grid 256 (full wave). Staging: thread -> (row, slot); slots are
// contiguous vector chunks so warps hit <=2 branch arms and loads are float4.
__global__ void __launch_bounds__(512) k_final(const float* __restrict__ goby_emb,
                                               const float* __restrict__ bool_emb,
                                               const float* __restrict__ count_emb,
                                               const float* __restrict__ W,
                                               const float* __restrict__ bias,
                                               const int* __restrict__ goby_idx,
                                               const int* __restrict__ is_indel,
                                               const int* __restrict__ matches_ref,
                                               const int* __restrict__ count_fwd,
                                               const int* __restrict__ count_rev,
                                               float* __restrict__ out) {
    const int tid = threadIdx.x;
    const int row0 = blockIdx.x * 16;
    __shared__ float fsh[16][240];

#pragma unroll
    for (int k = 0; k < 2; k++) {
        const int idx = tid + k * 512;          // 16 rows x 64 slots
        const int rr = idx >> 6;
        const int row = row0 + rr;
        const int slot = idx & 63;
        if (slot >= 4 && slot < 36) {           // g_m quads (from: 4-19, to: 20-35)
            int q = slot - 4;
            const float* src = (q < 16) ? &g_m[row * 64 + 4 * q]
                                        : &g_m[(BATCH + row) * 64 + 4 * (q - 16)];
            float4 v = *reinterpret_cast<const float4*>(src);
            int o = (q < 16) ? (8 + 4 * q) : (72 + 4 * (q - 16));
            *reinterpret_cast<float4*>(&fsh[rr][o]) = v;
        } else if (slot >= 36 && slot < 58) {   // nwf quads
            int q = slot - 36;
            int field = q >> 1;
            float4 v = *reinterpret_cast<const float4*>(
                &g_nwf[((field * BATCH) + row) * 8 + 4 * (q & 1)]);
            int o = 146 + 4 * q;                // byte-8 aligned in fsh -> two float2 stores
            *reinterpret_cast<float2*>(&fsh[rr][o])     = make_float2(v.x, v.y);
            *reinterpret_cast<float2*>(&fsh[rr][o + 2]) = make_float2(v.z, v.w);
        } else if (slot == 0) {                 // goby float4
            float4 v = *reinterpret_cast<const float4*>(&goby_emb[goby_idx[row] * 4]);
            *reinterpret_cast<float4*>(&fsh[rr][0]) = v;
        } else if (slot == 1) {                 // bools
            float2 bi = *reinterpret_cast<const float2*>(&bool_emb[is_indel[row] * 2]);
            float2 bm = *reinterpret_cast<const float2*>(&bool_emb[matches_ref[row] * 2]);
            *reinterpret_cast<float2*>(&fsh[rr][4]) = bi;
            *reinterpret_cast<float2*>(&fsh[rr][6]) = bm;
        } else if (slot == 2) {                 // count_fwd (5 floats, unaligned)
            const float* s = &count_emb[count_fwd[row] * 5];
#pragma unroll
            for (int j = 0; j < 5; j++) fsh[rr][136 + j] = s[j];
        } else if (slot == 3) {                 // count_rev
            const float* s = &count_emb[count_rev[row] * 5];
#pragma unroll
            for (int j = 0; j < 5; j++) fsh[rr][141 + j] = s[j];
        }
        // slots 58-63 idle
    }
    __syncthreads();

    const int rr = tid >> 5;          // row 0..15
    const int cp = tid & 31;          // col pair -> cols [2cp, 2cp+2)
    const float2* W2 = reinterpret_cast<const float2*>(W);
    float2 acc = __ldg(reinterpret_cast<const float2*>(bias) + cp);
#pragma unroll 6
    for (int f = 0; f < 234; f++) {
        float v = fsh[rr][f];
        float2 wv = __ldg(&W2[f * 32 + cp]);
        acc.x = fmaf(v, wv.x, acc.x);
        acc.y = fmaf(v, wv.y, acc.y);
    }
    *reinterpret_cast<float2*>(&out[(row0 + rr) * 64 + 2 * cp]) =
        make_float2(fmaxf(acc.x, 0.0f), fmaxf(acc.y, 0.0f));
}

// ---------------- launch (serial) ----------------
extern "C" void kernel_launch(void* const* d_in, const int* in_sizes, int n_in,
                              void* d_out, int out_size) {
    static const int dictmap[23]  = {0,1,2,3,4,5,6,7,8,9,10,11,12,13,14,15,16,17,18,19,20,21,22};
    static const int parammap[23] = {14,15,16,17,18,19,20,21,22,0,1,2,3,4,5,6,7,8,9,10,11,12,13};
    const int* mp = (in_sizes[0] == BATCH) ? dictmap : parammap;

    const int*   goby_idx     = (const int*)  d_in[mp[0]];
    const int*   is_indel     = (const int*)  d_in[mp[1]];
    const int*   matches_ref  = (const int*)  d_in[mp[2]];
    const int*   from_seq     = (const int*)  d_in[mp[3]];
    const int*   to_seq       = (const int*)  d_in[mp[4]];
    const int*   count_fwd    = (const int*)  d_in[mp[5]];
    const int*   count_rev    = (const int*)  d_in[mp[6]];
    const int*   nwf_numbers  = (const int*)  d_in[mp[7]];
    const int*   nwf_freqs    = (const int*)  d_in[mp[8]];
    const float* goby_emb     = (const float*)d_in[mp[9]];
    const float* bool_emb     = (const float*)d_in[mp[10]];
    const float* count_emb    = (const float*)d_in[mp[11]];
    const float* base_emb     = (const float*)d_in[mp[12]];
    const float* seq_Wx       = (const float*)d_in[mp[13]];
    const float* seq_Wh       = (const float*)d_in[mp[14]];
    const float* seq_b        = (const float*)d_in[mp[15]];
    const float* nwf_num_emb  = (const float*)d_in[mp[16]];
    const float* nwf_freq_emb = (const float*)d_in[mp[17]];
    const float* nwf_Wx       = (const float*)d_in[mp[18]];
    const float* nwf_Wh       = (const float*)d_in[mp[19]];
    const float* nwf_b        = (const float*)d_in[mp[20]];
    const float* reduce_W     = (const float*)d_in[mp[21]];
    const float* reduce_b     = (const float*)d_in[mp[22]];

    k_seq<<<(2 * BATCH) / SROWS, 256>>>(from_seq, to_seq, seq_Wh, seq_Wx, seq_b, base_emb);
    k_nwf<<<dim3(BATCH / 128, NFLD), 256>>>(nwf_numbers, nwf_freqs,
                                            nwf_num_emb, nwf_freq_emb,
                                            nwf_Wx, nwf_Wh, nwf_b);
    k_final<<<BATCH / 16, 512>>>(goby_emb, bool_emb, count_emb, reduce_W, reduce_b,
                                 goby_idx, is_indel, matches_ref, count_fwd, count_rev,
                                 (float*)d_out);
}

// round 16
// speedup vs baseline: 1.2931x; 1.0865x over previous
#include <cuda_runtime.h>
#include <cuda_fp16.h>

#define BATCH 4096
#define LSQ   64
#define HID   64
#define NFLD  11
#define LN    32
#define SROWS 32
#define SEQ_CTAS ((2 * BATCH) / SROWS)          // 256
#define NWF_CTAS (NFLD * (BATCH / 128))         // 352

// ---------------- scratch (no allocations allowed) ----------------
__device__ float g_m[2 * BATCH * HID];      // [from rows 0..4095 | to rows 4096..8191] x 64
__device__ float g_nwf[NFLD * BATCH * 8];   // [11][4096][8]

__constant__ int c_fm[11] = {0, 0, 1, 1, 2, 2, 3, 3, 4, 5, 5};

__device__ __forceinline__ float tanh_hw(float x) {
    float y; asm("tanh.approx.f32 %0, %1;" : "=f"(y) : "f"(x)); return y;
}
__device__ __forceinline__ float sig_hw(float x) {
    return fmaf(tanh_hw(0.5f * x), 0.5f, 0.5f);
}

// smem overlay: seq role ~20.5KB, nwf role ~40KB -> union sized by nwf
struct SeqS {
    __half  hbuf[2][SROWS][88];
    int     tok[SROWS][LSQ];
    __half2 ebase[85][3];
};
struct NwfS {
    int    ns[LN][132];
    int    fs[LN][132];
    __half At[8][16][24];
};
union MainS { SeqS s; NwfS n; };

// ================= fused kernel: seq CTAs (bid<256) + nwf CTAs =================
__global__ void __launch_bounds__(256, 2) k_main(
    const int* __restrict__ from_seq, const int* __restrict__ to_seq,
    const float* __restrict__ Wh, const float* __restrict__ Wx,
    const float* __restrict__ bias, const float* __restrict__ base_emb,
    const int* __restrict__ nums_g, const int* __restrict__ frs_g,
    const float* __restrict__ ne_g, const float* __restrict__ fe_g,
    const float* __restrict__ nWx_g, const float* __restrict__ nWh_g,
    const float* __restrict__ nb_g)
{
    __shared__ alignas(16) MainS sm;
    const int tid  = threadIdx.x;
    const int lane = tid & 31;
    const int w    = tid >> 5;
    const int gid  = lane >> 2;
    const int tig  = lane & 3;

    if (blockIdx.x < SEQ_CTAS) {
        // ---------------- seq role: proven 83us tensor-core LSTM ----------------
        SeqS* ss = &sm.s;
        const int row0 = blockIdx.x * SROWS;

        const int* seq = (row0 < BATCH) ? (from_seq + row0 * LSQ)
                                        : (to_seq + (row0 - BATCH) * LSQ);
        for (int i = tid; i < SROWS * LSQ; i += 256) ss->tok[i >> 6][i & 63] = seq[i];
        for (int i = tid; i < 2 * SROWS * 88; i += 256)
            (&ss->hbuf[0][0][0])[i] = __float2half(0.0f);
        for (int i = tid; i < 85 * 3; i += 256) {
            int v = i / 3, p = i % 3;
            ss->ebase[v][p] = __floats2half2_rn(base_emb[v * 6 + 2 * p], base_emb[v * 6 + 2 * p + 1]);
        }
        __syncthreads();
        if (tid < 64) ss->hbuf[tid >> 5][tid & 31][70] = __float2half(1.0f);
        if (tid < 96) {
            int r = tid / 3, p = tid % 3;
            *reinterpret_cast<__half2*>(&ss->hbuf[0][r][64 + 2 * p]) = ss->ebase[ss->tok[r][0]][p];
        }

        unsigned bfr[4][5][2];
#pragma unroll
        for (int g = 0; g < 4; g++) {
            const int col = 64 * g + 8 * w + gid;
#pragma unroll
            for (int kt = 0; kt < 4; kt++) {
                int k0 = 16 * kt + 2 * tig;
                __half2 b0 = __floats2half2_rn(Wh[k0 * 256 + col], Wh[(k0 + 1) * 256 + col]);
                __half2 b1 = __floats2half2_rn(Wh[(k0 + 8) * 256 + col], Wh[(k0 + 9) * 256 + col]);
                bfr[g][kt][0] = *reinterpret_cast<unsigned*>(&b0);
                bfr[g][kt][1] = *reinterpret_cast<unsigned*>(&b1);
            }
            {
                int r0 = 64 + 2 * tig;
                float v0 = (r0 < 70) ? Wx[(r0 - 64) * 256 + col] : ((r0 == 70) ? bias[col] : 0.0f);
                float v1 = (r0 + 1 < 70) ? Wx[(r0 - 63) * 256 + col] : ((r0 + 1 == 70) ? bias[col] : 0.0f);
                __half2 b0 = __floats2half2_rn(v0, v1);
                bfr[g][4][0] = *reinterpret_cast<unsigned*>(&b0);
                bfr[g][4][1] = 0u;
            }
        }

        const int hc0 = 8 * w + 2 * tig;
        const int arow = (lane < 16) ? lane : (lane - 16);
        const int acol = (lane < 16) ? 0 : 8;
        const unsigned a00 = (unsigned)__cvta_generic_to_shared(&ss->hbuf[0][arow][acol]);
        const unsigned a01 = (unsigned)__cvta_generic_to_shared(&ss->hbuf[0][16 + arow][acol]);
        const unsigned a10 = (unsigned)__cvta_generic_to_shared(&ss->hbuf[1][arow][acol]);
        const unsigned a11 = (unsigned)__cvta_generic_to_shared(&ss->hbuf[1][16 + arow][acol]);

        float cst[8] = {0.0f, 0.0f, 0.0f, 0.0f, 0.0f, 0.0f, 0.0f, 0.0f};

        __syncthreads();

        for (int t = 0; t < LSQ; t++) {
            const unsigned r0a = (t & 1) ? a10 : a00;
            const unsigned r1a = (t & 1) ? a11 : a01;

            float d0[4][4], d1[4][4];
#pragma unroll
            for (int g = 0; g < 4; g++)
#pragma unroll
                for (int q = 0; q < 4; q++) { d0[g][q] = 0.0f; d1[g][q] = 0.0f; }

#pragma unroll
            for (int kt = 0; kt < 5; kt++) {
                unsigned ah0[4], ah1[4];
                asm volatile("ldmatrix.sync.aligned.m8n8.x4.shared.b16 {%0,%1,%2,%3}, [%4];\n"
                             : "=r"(ah0[0]), "=r"(ah0[1]), "=r"(ah0[2]), "=r"(ah0[3])
                             : "r"(r0a + kt * 32));
                asm volatile("ldmatrix.sync.aligned.m8n8.x4.shared.b16 {%0,%1,%2,%3}, [%4];\n"
                             : "=r"(ah1[0]), "=r"(ah1[1]), "=r"(ah1[2]), "=r"(ah1[3])
                             : "r"(r1a + kt * 32));
#pragma unroll
                for (int g = 0; g < 4; g++) {
                    asm("mma.sync.aligned.m16n8k16.row.col.f32.f16.f16.f32 "
                        "{%0,%1,%2,%3},{%4,%5,%6,%7},{%8,%9},{%0,%1,%2,%3};\n"
                        : "+f"(d0[g][0]), "+f"(d0[g][1]), "+f"(d0[g][2]), "+f"(d0[g][3])
                        : "r"(ah0[0]), "r"(ah0[1]), "r"(ah0[2]), "r"(ah0[3]),
                          "r"(bfr[g][kt][0]), "r"(bfr[g][kt][1]));
                    asm("mma.sync.aligned.m16n8k16.row.col.f32.f16.f16.f32 "
                        "{%0,%1,%2,%3},{%4,%5,%6,%7},{%8,%9},{%0,%1,%2,%3};\n"
                        : "+f"(d1[g][0]), "+f"(d1[g][1]), "+f"(d1[g][2]), "+f"(d1[g][3])
                        : "r"(ah1[0]), "r"(ah1[1]), "r"(ah1[2]), "r"(ah1[3]),
                          "r"(bfr[g][kt][0]), "r"(bfr[g][kt][1]));
                }
            }

            float hv[8];
#pragma unroll
            for (int q = 0; q < 4; q++) {
                cst[q] = sig_hw(d0[1][q]) * cst[q] + sig_hw(d0[0][q]) * tanh_hw(d0[2][q]);
                hv[q]  = sig_hw(d0[3][q]) * tanh_hw(cst[q]);
            }
#pragma unroll
            for (int q = 0; q < 4; q++) {
                cst[4 + q] = sig_hw(d1[1][q]) * cst[4 + q] + sig_hw(d1[0][q]) * tanh_hw(d1[2][q]);
                hv[4 + q]  = sig_hw(d1[3][q]) * tanh_hw(cst[4 + q]);
            }

            const int wb = (t & 1) ^ 1;
            *reinterpret_cast<__half2*>(&ss->hbuf[wb][gid][hc0])      = __floats2half2_rn(hv[0], hv[1]);
            *reinterpret_cast<__half2*>(&ss->hbuf[wb][gid + 8][hc0])  = __floats2half2_rn(hv[2], hv[3]);
            *reinterpret_cast<__half2*>(&ss->hbuf[wb][gid + 16][hc0]) = __floats2half2_rn(hv[4], hv[5]);
            *reinterpret_cast<__half2*>(&ss->hbuf[wb][gid + 24][hc0]) = __floats2half2_rn(hv[6], hv[7]);
            if (t < LSQ - 1 && tid < 96) {
                int r = tid / 3, p = tid % 3;
                *reinterpret_cast<__half2*>(&ss->hbuf[wb][r][64 + 2 * p]) = ss->ebase[ss->tok[r][t + 1]][p];
            }

            if (t == LSQ - 1) {
                *reinterpret_cast<float2*>(&g_m[(row0 + gid) * 64 + hc0])      = make_float2(hv[0], hv[1]);
                *reinterpret_cast<float2*>(&g_m[(row0 + gid + 8) * 64 + hc0])  = make_float2(hv[2], hv[3]);
                *reinterpret_cast<float2*>(&g_m[(row0 + gid + 16) * 64 + hc0]) = make_float2(hv[4], hv[5]);
                *reinterpret_cast<float2*>(&g_m[(row0 + gid + 24) * 64 + hc0]) = make_float2(hv[6], hv[7]);
            }
            __syncthreads();
        }
    } else {
        // ---------------- nwf role: proven tensor-core NWF LSTMs ----------------
        NwfS* ns = &sm.n;
        const int bi = blockIdx.x - SEQ_CTAS;   // 0..351
        const int field = bi >> 5;              // 11 fields x 32 tiles
        const int tile  = bi & 31;
        const int m = c_fm[field];
        const int row0 = tile * 128;

        const int base = (field * BATCH + row0) * LN;
        for (int i = tid; i < 128 * LN; i += 256) {
            int r = i >> 5, t = i & 31;
            ns->ns[t][r] = nums_g[base + i];
            ns->fs[t][r] = frs_g[base + i];
        }
        for (int i = tid; i < 8 * 16 * 24 / 2; i += 256)
            reinterpret_cast<__half2*>(&ns->At[0][0][0])[i] = __floats2half2_rn(0.0f, 0.0f);
        __syncthreads();

        unsigned bf[4][2];
        float2 b2[4];
#pragma unroll
        for (int g = 0; g < 4; g++) {
            const int col = 8 * g + gid;
            __half2 x0 = __floats2half2_rn(nWx_g[m * 256 + (2 * tig) * 32 + col],
                                           nWx_g[m * 256 + (2 * tig + 1) * 32 + col]);
            __half2 h0 = __floats2half2_rn(nWh_g[m * 256 + (2 * tig) * 32 + col],
                                           nWh_g[m * 256 + (2 * tig + 1) * 32 + col]);
            bf[g][0] = *reinterpret_cast<unsigned*>(&x0);
            bf[g][1] = *reinterpret_cast<unsigned*>(&h0);
            b2[g] = make_float2(nb_g[m * 32 + 8 * g + 2 * tig], nb_g[m * 32 + 8 * g + 2 * tig + 1]);
        }

        const float4* neg = reinterpret_cast<const float4*>(ne_g) + m * 1000;
        const float4* feg = reinterpret_cast<const float4*>(fe_g) + m * 1000;

        const int lrow = lane & 15;
        const bool isNe = (lane < 16);
        const int myrow = w * 16 + lrow;
        const int xcol = isNe ? 0 : 4;
        const unsigned aaddr = (unsigned)__cvta_generic_to_shared(&ns->At[w][lrow][isNe ? 0 : 8]);

        float cst[4] = {0.0f, 0.0f, 0.0f, 0.0f};
        float hv[4] = {0.0f, 0.0f, 0.0f, 0.0f};

        for (int t = 0; t < LN; t++) {
            int idx = isNe ? ns->ns[t][myrow] : ns->fs[t][myrow];
            float4 v = __ldg(isNe ? &neg[idx] : &feg[idx]);
            *reinterpret_cast<__half2*>(&ns->At[w][lrow][xcol])     = __floats2half2_rn(v.x, v.y);
            *reinterpret_cast<__half2*>(&ns->At[w][lrow][xcol + 2]) = __floats2half2_rn(v.z, v.w);
            __syncwarp();

            unsigned a[4];
            asm volatile("ldmatrix.sync.aligned.m8n8.x4.shared.b16 {%0,%1,%2,%3}, [%4];\n"
                         : "=r"(a[0]), "=r"(a[1]), "=r"(a[2]), "=r"(a[3]) : "r"(aaddr));

            float d[4][4];
#pragma unroll
            for (int g = 0; g < 4; g++) {
                d[g][0] = 0.0f; d[g][1] = 0.0f; d[g][2] = 0.0f; d[g][3] = 0.0f;
                asm("mma.sync.aligned.m16n8k16.row.col.f32.f16.f16.f32 "
                    "{%0,%1,%2,%3},{%4,%5,%6,%7},{%8,%9},{%0,%1,%2,%3};\n"
                    : "+f"(d[g][0]), "+f"(d[g][1]), "+f"(d[g][2]), "+f"(d[g][3])
                    : "r"(a[0]), "r"(a[1]), "r"(a[2]), "r"(a[3]),
                      "r"(bf[g][0]), "r"(bf[g][1]));
            }

#pragma unroll
            for (int q = 0; q < 4; q++) {
                float bi2 = (q & 1) ? b2[0].y : b2[0].x;
                float bff = (q & 1) ? b2[1].y : b2[1].x;
                float bgg = (q & 1) ? b2[2].y : b2[2].x;
                float bo = (q & 1) ? b2[3].y : b2[3].x;
                float gi = d[0][q] + bi2, gf = d[1][q] + bff, gg = d[2][q] + bgg, go = d[3][q] + bo;
                cst[q] = sig_hw(gf) * cst[q] + sig_hw(gi) * tanh_hw(gg);
                hv[q]  = sig_hw(go) * tanh_hw(cst[q]);
            }

            *reinterpret_cast<__half2*>(&ns->At[w][gid][8 + 2 * tig])     = __floats2half2_rn(hv[0], hv[1]);
            *reinterpret_cast<__half2*>(&ns->At[w][gid + 8][8 + 2 * tig]) = __floats2half2_rn(hv[2], hv[3]);
        }

        float* o = &g_nwf[(field * BATCH + row0 + w * 16) * 8];
        *reinterpret_cast<float2*>(&o[gid * 8 + 2 * tig])       = make_float2(hv[0], hv[1]);
        *reinterpret_cast<float2*>(&o[(gid + 8) * 8 + 2 * tig]) = make_float2(hv[2], hv[3]);
    }
}

// ---------------- kernel 2: slot-staged concat + dense 234->64 + ReLU (R15) ----------------
__global__ void __launch_bounds__(512) k_final(const float* __restrict__ goby_emb,
                                               const float* __restrict__ bool_emb,
                                               const float* __restrict__ count_emb,
                                               const float* __restrict__ W,
                                               const float* __restrict__ bias,
                                               const int* __restrict__ goby_idx,
                                               const int* __restrict__ is_indel,
                                               const int* __restrict__ matches_ref,
                                               const int* __restrict__ count_fwd,
                                               const int* __restrict__ count_rev,
                                               float* __restrict__ out) {
    const int tid = threadIdx.x;
    const int row0 = blockIdx.x * 16;
    __shared__ float fsh[16][240];

#pragma unroll
    for (int k = 0; k < 2; k++) {
        const int idx = tid + k * 512;
        const int rr = idx >> 6;
        const int row = row0 + rr;
        const int slot = idx & 63;
        if (slot >= 4 && slot < 36) {
            int q = slot - 4;
            const float* src = (q < 16) ? &g_m[row * 64 + 4 * q]
                                        : &g_m[(BATCH + row) * 64 + 4 * (q - 16)];
            float4 v = *reinterpret_cast<const float4*>(src);
            int o = (q < 16) ? (8 + 4 * q) : (72 + 4 * (q - 16));
            *reinterpret_cast<float4*>(&fsh[rr][o]) = v;
        } else if (slot >= 36 && slot < 58) {
            int q = slot - 36;
            int field = q >> 1;
            float4 v = *reinterpret_cast<const float4*>(
                &g_nwf[((field * BATCH) + row) * 8 + 4 * (q & 1)]);
            int o = 146 + 4 * q;
            *reinterpret_cast<float2*>(&fsh[rr][o])     = make_float2(v.x, v.y);
            *reinterpret_cast<float2*>(&fsh[rr][o + 2]) = make_float2(v.z, v.w);
        } else if (slot == 0) {
            float4 v = *reinterpret_cast<const float4*>(&goby_emb[goby_idx[row] * 4]);
            *reinterpret_cast<float4*>(&fsh[rr][0]) = v;
        } else if (slot == 1) {
            float2 bi = *reinterpret_cast<const float2*>(&bool_emb[is_indel[row] * 2]);
            float2 bm = *reinterpret_cast<const float2*>(&bool_emb[matches_ref[row] * 2]);
            *reinterpret_cast<float2*>(&fsh[rr][4]) = bi;
            *reinterpret_cast<float2*>(&fsh[rr][6]) = bm;
        } else if (slot == 2) {
            const float* s = &count_emb[count_fwd[row] * 5];
#pragma unroll
            for (int j = 0; j < 5; j++) fsh[rr][136 + j] = s[j];
        } else if (slot == 3) {
            const float* s = &count_emb[count_rev[row] * 5];
#pragma unroll
            for (int j = 0; j < 5; j++) fsh[rr][141 + j] = s[j];
        }
    }
    __syncthreads();

    const int rr = tid >> 5;
    const int cp = tid & 31;
    const float2* W2 = reinterpret_cast<const float2*>(W);
    float2 acc = __ldg(reinterpret_cast<const float2*>(bias) + cp);
#pragma unroll 6
    for (int f = 0; f < 234; f++) {
        float v = fsh[rr][f];
        float2 wv = __ldg(&W2[f * 32 + cp]);
        acc.x = fmaf(v, wv.x, acc.x);
        acc.y = fmaf(v, wv.y, acc.y);
    }
    *reinterpret_cast<float2*>(&out[(row0 + rr) * 64 + 2 * cp]) =
        make_float2(fmaxf(acc.x, 0.0f), fmaxf(acc.y, 0.0f));
}

// ---------------- launch ----------------
extern "C" void kernel_launch(void* const* d_in, const int* in_sizes, int n_in,
                              void* d_out, int out_size) {
    static const int dictmap[23]  = {0,1,2,3,4,5,6,7,8,9,10,11,12,13,14,15,16,17,18,19,20,21,22};
    static const int parammap[23] = {14,15,16,17,18,19,20,21,22,0,1,2,3,4,5,6,7,8,9,10,11,12,13};
    const int* mp = (in_sizes[0] == BATCH) ? dictmap : parammap;

    const int*   goby_idx     = (const int*)  d_in[mp[0]];
    const int*   is_indel     = (const int*)  d_in[mp[1]];
    const int*   matches_ref  = (const int*)  d_in[mp[2]];
    const int*   from_seq     = (const int*)  d_in[mp[3]];
    const int*   to_seq       = (const int*)  d_in[mp[4]];
    const int*   count_fwd    = (const int*)  d_in[mp[5]];
    const int*   count_rev    = (const int*)  d_in[mp[6]];
    const int*   nwf_numbers  = (const int*)  d_in[mp[7]];
    const int*   nwf_freqs    = (const int*)  d_in[mp[8]];
    const float* goby_emb     = (const float*)d_in[mp[9]];
    const float* bool_emb     = (const float*)d_in[mp[10]];
    const float* count_emb    = (const float*)d_in[mp[11]];
    const float* base_emb     = (const float*)d_in[mp[12]];
    const float* seq_Wx       = (const float*)d_in[mp[13]];
    const float* seq_Wh       = (const float*)d_in[mp[14]];
    const float* seq_b        = (const float*)d_in[mp[15]];
    const float* nwf_num_emb  = (const float*)d_in[mp[16]];
    const float* nwf_freq_emb = (const float*)d_in[mp[17]];
    const float* nwf_Wx       = (const float*)d_in[mp[18]];
    const float* nwf_Wh       = (const float*)d_in[mp[19]];
    const float* nwf_b        = (const float*)d_in[mp[20]];
    const float* reduce_W     = (const float*)d_in[mp[21]];
    const float* reduce_b     = (const float*)d_in[mp[22]];

    k_main<<<SEQ_CTAS + NWF_CTAS, 256>>>(from_seq, to_seq, seq_Wh, seq_Wx, seq_b, base_emb,
                                         nwf_numbers, nwf_freqs, nwf_num_emb, nwf_freq_emb,
                                         nwf_Wx, nwf_Wh, nwf_b);
    k_final<<<BATCH / 16, 512>>>(goby_emb, bool_emb, count_emb, reduce_W, reduce_b,
                                 goby_idx, is_indel, matches_ref, count_fwd, count_rev,
                                 (float*)d_out);
}